// round 12
// baseline (speedup 1.0000x reference)
#include <cuda_runtime.h>
#include <cuda_fp16.h>
#include <math.h>
#include <cstdint>

// NTXent loss, 2B = 8192, D = 128.  SINGLE-LAUNCH megakernel:
//   phase 0: CTAs 0..63 normalize one 128-row block each (-> fp16, scaled)
//   gate   : all 288 CTAs spin until all 64 blocks normalized
//   phase 1: strip-mined symmetric fp16 HMMA GEMM (f16 acc), exp row/col sums
//   phase 2: last 32 finishing CTAs each finalize a 256-row slice; final CTA
//            reduces 32 partials in fixed order, writes out, resets counters.
// Inputs pre-scaled by sqrt(2*log2(e)) so acc == ex2 argument.

#define TWO_B   8192
#define DIM     128
#define NBLK    64
#define NCTA    288           // sum over octets o: (8-o)*8
#define NSLOT   72            // 8 row-sum slots + 64 col-sum slots
#define NFIN    32            // finalize slices (256 rows each)

__device__ __half g_Xh[TWO_B * DIM];            // normalized*sqrt(C2) fp16 (MMA)
__device__ float  g_inorm[TWO_B];               // 1/||e_i||
__device__ float  g_part[NSLOT][TWO_B];         // [slot][row] partials (unused stay 0)
__device__ float  g_bpart[NFIN];                // per-slice loss partials
__device__ int    g_norm;                       // normalize-done counter
__device__ int    g_count;                      // gemm-done counter
__device__ int    g_count2;                     // finalize-done counter

// C2 = 2*log2(e); SQC2 = sqrt(C2)
#define SQC2 1.6986435838704467f

// ---------------------------------------------------------------------------
// helpers
// ---------------------------------------------------------------------------
__device__ __forceinline__ uint32_t smem_u32(const void* p) {
    uint32_t a;
    asm("{ .reg .u64 t; cvta.to.shared.u64 t, %1; cvt.u32.u64 %0, t; }" : "=r"(a) : "l"(p));
    return a;
}
__device__ __forceinline__ void cp16(uint32_t saddr, const void* g) {
    asm volatile("cp.async.cg.shared.global [%0], [%1], 16;" :: "r"(saddr), "l"(g));
}
#define CP_COMMIT() asm volatile("cp.async.commit_group;" ::: "memory")
#define CP_WAIT0()  asm volatile("cp.async.wait_group 0;" ::: "memory")

__device__ __forceinline__ void ldsm4(uint32_t* r, uint32_t addr) {
    asm volatile("ldmatrix.sync.aligned.m8n8.x4.shared.b16 {%0,%1,%2,%3}, [%4];"
                 : "=r"(r[0]), "=r"(r[1]), "=r"(r[2]), "=r"(r[3]) : "r"(addr));
}
__device__ __forceinline__ void mma16816h(uint32_t* d, const uint32_t* a, uint32_t b0, uint32_t b1) {
    asm volatile("mma.sync.aligned.m16n8k16.row.col.f16.f16.f16.f16 "
                 "{%0,%1}, {%2,%3,%4,%5}, {%6,%7}, {%0,%1};"
                 : "+r"(d[0]), "+r"(d[1])
                 : "r"(a[0]), "r"(a[1]), "r"(a[2]), "r"(a[3]), "r"(b0), "r"(b1));
}
__device__ __forceinline__ uint32_t hex2(uint32_t x) {
    uint32_t y; asm("ex2.approx.f16x2 %0, %1;" : "=r"(y) : "r"(x)); return y;
}
__device__ __forceinline__ uint32_t hadd2(uint32_t a, uint32_t b) {
    uint32_t y; asm("add.rn.f16x2 %0, %1, %2;" : "=r"(y) : "r"(a), "r"(b)); return y;
}
__device__ __forceinline__ float2 h2f(uint32_t r) {
    __half2 h = *reinterpret_cast<__half2*>(&r);
    return __half22float2(h);
}
__device__ __forceinline__ float ex2f(float x) {
    float y; asm("ex2.approx.ftz.f32 %0, %1;" : "=f"(y) : "f"(x)); return y;
}

// ---------------------------------------------------------------------------
#define SROWB   272                        // smem row stride (17*16 B)
#define TILE_B  (128 * SROWB)              // 34816
#define SM_A    0
#define SM_B0   TILE_B
#define SM_B1   (2 * TILE_B)
#define SM_RED  (3 * TILE_B)               // colred[4][128] / rowred[2][128] / sm[256]
#define SM_TOT  (SM_RED + 4 * 128 * 4)

__global__ void __launch_bounds__(256, 2) fused_kernel(
        const float* __restrict__ E, const int* __restrict__ labels,
        float* __restrict__ out) {
    extern __shared__ __align__(16) char smem[];
    const uint32_t sb = smem_u32(smem);
    const int tid  = threadIdx.x;
    const int lane = tid & 31;
    const int warp = tid >> 5;
    const int wm = warp >> 1;              // 0..3
    const int wn = warp & 1;               // 0..1

    // ---- phase 0: normalize (CTAs 0..63, one 128-row block each) ----
    if (blockIdx.x < NBLK) {
        const int rb = blockIdx.x * 128;
        #pragma unroll 4
        for (int it = 0; it < 16; ++it) {
            int row = rb + warp * 16 + it;
            const float4 v = *reinterpret_cast<const float4*>(&E[row * DIM + lane * 4]);
            float ss = v.x * v.x + v.y * v.y + v.z * v.z + v.w * v.w;
            #pragma unroll
            for (int o = 16; o > 0; o >>= 1) ss += __shfl_xor_sync(0xffffffffu, ss, o);
            float inv = rsqrtf(fmaxf(ss, 1e-24f));
            if (lane == 0) g_inorm[row] = inv;
            float s = inv * SQC2;
            __half2 h0 = __float22half2_rn(make_float2(v.x * s, v.y * s));
            __half2 h1 = __float22half2_rn(make_float2(v.z * s, v.w * s));
            uint2 pk = { *reinterpret_cast<uint32_t*>(&h0), *reinterpret_cast<uint32_t*>(&h1) };
            *reinterpret_cast<uint2*>(&g_Xh[row * DIM + lane * 4]) = pk;
        }
        __syncthreads();
        __threadfence();
        if (tid == 0) atomicAdd(&g_norm, 1);
    }

    // ---- gate: wait for all blocks normalized ----
    if (tid == 0) {
        while (atomicAdd(&g_norm, 0) < NBLK) {}
    }
    __syncthreads();
    __threadfence();

    // ---- decode blockIdx -> (I, c): octet o of I, chunks c = o..7 ----
    int t = blockIdx.x, o = 0;
    for (;;) { int n = (8 - o) * 8; if (t < n) break; t -= n; ++o; }
    const int c  = o + (t >> 3);
    const int I  = 8 * o + (t & 7);
    const int J0 = max(8 * c, I);
    const int L  = 8 * c + 8 - J0;         // strip length (1..8)
    const int rowBase = I * 128;

    const char* __restrict__ Xb = reinterpret_cast<const char*>(g_Xh);

    auto loadTile = [&](uint32_t dst, int gRow) {
        #pragma unroll
        for (int i = 0; i < 8; ++i) {
            int f = tid + i * 256;
            int r = f >> 4, cc = (f & 15) << 4;
            cp16(dst + r * SROWB + cc, Xb + (size_t)(gRow + r) * 256 + cc);
        }
    };

    loadTile(sb + SM_A, rowBase);
    loadTile(sb + SM_B0, J0 * 128);
    CP_COMMIT();

    const uint32_t aBase = sb + SM_A + (uint32_t)(wm * 32 + (lane & 15)) * SROWB + ((lane >> 4) << 4);
    const uint32_t bOff  = (uint32_t)(wn * 64 + (lane & 15)) * SROWB + ((lane >> 4) << 4);

    float rs32[4] = {0.f, 0.f, 0.f, 0.f};  // strip row sums (fp32)
    float* colred = reinterpret_cast<float*>(smem + SM_RED);   // [4][128]

    for (int k = 0; k < L; ++k) {
        const int J = J0 + k;
        CP_WAIT0();
        __syncthreads();   // B(k) resident; prev tile's colred reads done

        if (k + 1 < L) {
            loadTile(sb + (((k + 1) & 1) ? SM_B1 : SM_B0), (J + 1) * 128);
            CP_COMMIT();
        }

        const uint32_t bBase = sb + ((k & 1) ? SM_B1 : SM_B0) + bOff;

        uint32_t acc[2][8][2];             // f16x2 accumulators
        #pragma unroll
        for (int m = 0; m < 2; ++m)
            #pragma unroll
            for (int n = 0; n < 8; ++n) { acc[m][n][0] = 0u; acc[m][n][1] = 0u; }

        #pragma unroll
        for (int ks = 0; ks < 8; ++ks) {
            uint32_t a[2][4], b[4][4];
            #pragma unroll
            for (int m = 0; m < 2; ++m)
                ldsm4(a[m], aBase + m * (16 * SROWB) + ks * 32);
            #pragma unroll
            for (int n4 = 0; n4 < 4; ++n4)
                ldsm4(b[n4], bBase + n4 * (16 * SROWB) + ks * 32);
            #pragma unroll
            for (int m = 0; m < 2; ++m)
                #pragma unroll
                for (int n4 = 0; n4 < 4; ++n4) {
                    mma16816h(acc[m][n4 * 2 + 0], a[m], b[n4][0], b[n4][2]);
                    mma16816h(acc[m][n4 * 2 + 1], a[m], b[n4][1], b[n4][3]);
                }
        }

        // epilogue: packed e = ex2(acc); row sums + column sums
        uint32_t cs[8];
        #pragma unroll
        for (int n = 0; n < 8; ++n) cs[n] = 0u;

        #pragma unroll
        for (int m = 0; m < 2; ++m) {
            uint32_t rsp[2] = {0u, 0u};
            #pragma unroll
            for (int n = 0; n < 8; ++n) {
                uint32_t e0 = hex2(acc[m][n][0]);
                uint32_t e1 = hex2(acc[m][n][1]);
                rsp[0] = hadd2(rsp[0], e0);
                rsp[1] = hadd2(rsp[1], e1);
                cs[n] = hadd2(cs[n], hadd2(e0, e1));
            }
            #pragma unroll
            for (int g = 0; g < 2; ++g) {
                float2 f = h2f(rsp[g]);
                rs32[m * 2 + g] += f.x + f.y;
            }
        }

        if (J != I) {
            #pragma unroll
            for (int n = 0; n < 8; ++n) {
                cs[n] = hadd2(cs[n], __shfl_xor_sync(0xffffffffu, cs[n], 4));
                cs[n] = hadd2(cs[n], __shfl_xor_sync(0xffffffffu, cs[n], 8));
                cs[n] = hadd2(cs[n], __shfl_xor_sync(0xffffffffu, cs[n], 16));
            }
            if (lane < 4) {
                #pragma unroll
                for (int n = 0; n < 8; ++n) {
                    int cc = wn * 64 + (n >> 1) * 16 + (n & 1) * 8 + lane * 2;
                    float2 f = h2f(cs[n]);
                    *reinterpret_cast<float2*>(&colred[wm * 128 + cc]) = f;
                }
            }
            __syncthreads();
            if (tid < 128) {
                float ct = colred[tid] + colred[128 + tid] +
                           colred[256 + tid] + colred[384 + tid];
                g_part[8 + I][J * 128 + tid] = ct;
            }
        } else {
            __syncthreads();   // keep barrier count uniform
        }
    }

    // strip row sums
    #pragma unroll
    for (int u = 0; u < 4; ++u) {
        rs32[u] += __shfl_xor_sync(0xffffffffu, rs32[u], 1);
        rs32[u] += __shfl_xor_sync(0xffffffffu, rs32[u], 2);
    }
    float* rowred = reinterpret_cast<float*>(smem + SM_RED);   // [2][128]
    __syncthreads();
    if ((lane & 3) == 0) {
        #pragma unroll
        for (int u = 0; u < 4; ++u) {
            int r = wm * 32 + (u >> 1) * 16 + (u & 1) * 8 + (lane >> 2);
            rowred[wn * 128 + r] = rs32[u];
        }
    }
    __syncthreads();
    if (tid < 128)
        g_part[c][rowBase + tid] = rowred[tid] + rowred[128 + tid];

    // ---- phase 2: last 32 finishers finalize 256-row slices ----
    __shared__ int s_slice;
    __syncthreads();           // g_part stores issued by all threads
    if (tid == 0) {
        __threadfence();
        int cdone = atomicAdd(&g_count, 1);       // 0..NCTA-1
        s_slice = cdone - (NCTA - NFIN);
    }
    __syncthreads();
    const int slice = s_slice;
    if (slice < 0) return;

    if (tid == 0) {
        while (atomicAdd(&g_count, 0) < NCTA) {}  // all partials published
    }
    __syncthreads();
    __threadfence();

    const int i = slice * 256 + tid;

    float R = 0.f;
    #pragma unroll 8
    for (int s = 0; s < NSLOT; ++s) R += g_part[s][i];

    int pos = (i < TWO_B / 2) ? (i + TWO_B / 2) : (i - TWO_B / 2);
    int a = min(i, pos), b = max(i, pos);
    int l = labels[i];
    int j = l + (l >= a ? 1 : 0);
    j += (j >= b ? 1 : 0);

    // exact fp32 picked logit from raw E + inverse norms
    const float* ei = E + (size_t)i * DIM;
    const float* ej = E + (size_t)j * DIM;
    float dq = 0.f;
    #pragma unroll
    for (int k = 0; k < DIM; k += 4) {
        float4 vi = *reinterpret_cast<const float4*>(&ei[k]);
        float4 vj = *reinterpret_cast<const float4*>(&ej[k]);
        dq += vi.x * vj.x + vi.y * vj.y + vi.z * vj.z + vi.w * vj.w;
    }
    float q = 2.0f * dq * g_inorm[i] * g_inorm[j];

    // fp16-consistent diagonal + positive-pair terms (scaled: acc == ex2 arg)
    float dii = 0.f, dpp = 0.f;
    const __half* hi = g_Xh + (size_t)i   * DIM;
    const __half* hp = g_Xh + (size_t)pos * DIM;
    #pragma unroll
    for (int k = 0; k < DIM; k += 2) {
        float2 a2 = __half22float2(*reinterpret_cast<const __half2*>(&hi[k]));
        float2 b2 = __half22float2(*reinterpret_cast<const __half2*>(&hp[k]));
        dii += a2.x * a2.x + a2.y * a2.y;
        dpp += a2.x * b2.x + a2.y * b2.y;
    }

    float masked = R - ex2f(dii) - ex2f(dpp);
    float loss = logf(masked) - q;

    // deterministic block reduce
    float* sm = reinterpret_cast<float*>(smem + SM_RED);
    sm[tid] = loss;
    __syncthreads();
    #pragma unroll
    for (int off = 128; off > 0; off >>= 1) {
        if (tid < off) sm[tid] += sm[tid + off];
        __syncthreads();
    }
    if (tid == 0) {
        g_bpart[slice] = sm[0];
        __threadfence();
        int c2 = atomicAdd(&g_count2, 1);
        if (c2 == NFIN - 1) {                     // all slices published
            float s = 0.f;
            #pragma unroll
            for (int bb = 0; bb < NFIN; ++bb) s += g_bpart[bb];
            out[0] = s / (float)TWO_B;
            g_count = 0; g_count2 = 0; g_norm = 0;  // reset for graph replay
        }
    }
}

// ---------------------------------------------------------------------------
extern "C" void kernel_launch(void* const* d_in, const int* in_sizes, int n_in,
                              void* d_out, int out_size) {
    const float* E      = (const float*)d_in[0];
    const int*   labels = (const int*)d_in[1];
    float* out = (float*)d_out;

    cudaFuncSetAttribute(fused_kernel,
                         cudaFuncAttributeMaxDynamicSharedMemorySize, SM_TOT);
    fused_kernel<<<NCTA, 256, SM_TOT>>>(E, labels, out);
}

// round 13
// speedup vs baseline: 1.2674x; 1.2674x over previous
#include <cuda_runtime.h>
#include <cuda_fp16.h>
#include <math.h>
#include <cstdint>

// NTXent loss, 2B = 8192, D = 128.
// Symmetric fp16 HMMA GEMM (f16 acc), strip-mined upper-triangle blocks.
// 128 threads/CTA, warp tile 64x64 (2x2 warps) for max ILP per warp.
// Inputs pre-scaled by sqrt(2*log2(e)) so acc == ex2 argument.
// 3 launches: normalize -> gemm -> fused finalize+reduce (last-block).

#define TWO_B   8192
#define DIM     128
#define NBLK    64
#define NCTA    288           // sum over octets o: (8-o)*8
#define NSLOT   72            // 8 row-sum slots + 64 col-sum slots
#define NFBLK   32            // finalize blocks

__device__ __half g_Xh[TWO_B * DIM];            // normalized*sqrt(C2) fp16 (MMA)
__device__ float  g_inorm[TWO_B];               // 1/||e_i||
__device__ float  g_part[NSLOT][TWO_B];         // [slot][row] partials (unused stay 0)
__device__ float  g_bpart[NFBLK];               // per-block loss partials
__device__ int    g_count;                      // last-block counter (self-resetting)

// C2 = 2*log2(e); SQC2 = sqrt(C2)
#define SQC2 1.6986435838704467f

// ---------------------------------------------------------------------------
// helpers
// ---------------------------------------------------------------------------
__device__ __forceinline__ uint32_t smem_u32(const void* p) {
    uint32_t a;
    asm("{ .reg .u64 t; cvta.to.shared.u64 t, %1; cvt.u32.u64 %0, t; }" : "=r"(a) : "l"(p));
    return a;
}
__device__ __forceinline__ void cp16(uint32_t saddr, const void* g) {
    asm volatile("cp.async.cg.shared.global [%0], [%1], 16;" :: "r"(saddr), "l"(g));
}
#define CP_COMMIT() asm volatile("cp.async.commit_group;" ::: "memory")
#define CP_WAIT0()  asm volatile("cp.async.wait_group 0;" ::: "memory")

__device__ __forceinline__ void ldsm4(uint32_t* r, uint32_t addr) {
    asm volatile("ldmatrix.sync.aligned.m8n8.x4.shared.b16 {%0,%1,%2,%3}, [%4];"
                 : "=r"(r[0]), "=r"(r[1]), "=r"(r[2]), "=r"(r[3]) : "r"(addr));
}
__device__ __forceinline__ void mma16816h(uint32_t* d, const uint32_t* a, uint32_t b0, uint32_t b1) {
    asm volatile("mma.sync.aligned.m16n8k16.row.col.f16.f16.f16.f16 "
                 "{%0,%1}, {%2,%3,%4,%5}, {%6,%7}, {%0,%1};"
                 : "+r"(d[0]), "+r"(d[1])
                 : "r"(a[0]), "r"(a[1]), "r"(a[2]), "r"(a[3]), "r"(b0), "r"(b1));
}
__device__ __forceinline__ uint32_t hex2(uint32_t x) {
    uint32_t y; asm("ex2.approx.f16x2 %0, %1;" : "=r"(y) : "r"(x)); return y;
}
__device__ __forceinline__ uint32_t hadd2(uint32_t a, uint32_t b) {
    uint32_t y; asm("add.rn.f16x2 %0, %1, %2;" : "=r"(y) : "r"(a), "r"(b)); return y;
}
__device__ __forceinline__ float2 h2f(uint32_t r) {
    __half2 h = *reinterpret_cast<__half2*>(&r);
    return __half22float2(h);
}
__device__ __forceinline__ float ex2f(float x) {
    float y; asm("ex2.approx.ftz.f32 %0, %1;" : "=f"(y) : "f"(x)); return y;
}

// ---------------------------------------------------------------------------
// 1) Row-normalize -> scaled fp16 + inverse norms. One warp per row.
// ---------------------------------------------------------------------------
__global__ void __launch_bounds__(256) normalize_kernel(const float* __restrict__ E) {
    int warp = threadIdx.x >> 5, lane = threadIdx.x & 31;
    int row = blockIdx.x * 8 + warp;
    const float4 v = *reinterpret_cast<const float4*>(&E[row * DIM + lane * 4]);
    float ss = v.x * v.x + v.y * v.y + v.z * v.z + v.w * v.w;
    #pragma unroll
    for (int o = 16; o > 0; o >>= 1) ss += __shfl_xor_sync(0xffffffffu, ss, o);
    float inv = rsqrtf(fmaxf(ss, 1e-24f));
    if (lane == 0) g_inorm[row] = inv;
    float s = inv * SQC2;
    __half2 h0 = __float22half2_rn(make_float2(v.x * s, v.y * s));
    __half2 h1 = __float22half2_rn(make_float2(v.z * s, v.w * s));
    uint2 pk = { *reinterpret_cast<uint32_t*>(&h0), *reinterpret_cast<uint32_t*>(&h1) };
    *reinterpret_cast<uint2*>(&g_Xh[row * DIM + lane * 4]) = pk;
}

// ---------------------------------------------------------------------------
// 2) Strip-mined symmetric HMMA GEMM (f16 acc) + exp row/col sums.
//    128 threads = 4 warps (wm 0..1 x wn 0..1); warp tile 64x64; K=128.
// ---------------------------------------------------------------------------
#define SROWB   272                        // smem row stride (17*16 B)
#define TILE_B  (128 * SROWB)              // 34816
#define SM_A    0
#define SM_B0   TILE_B
#define SM_B1   (2 * TILE_B)
#define SM_RED  (3 * TILE_B)               // colred[2][128] / rowred[2][128]
#define SM_TOT  (SM_RED + 2 * 128 * 4)

__global__ void __launch_bounds__(128, 2) gemm_sym_kernel() {
    extern __shared__ __align__(16) char smem[];
    const uint32_t sb = smem_u32(smem);
    const int tid  = threadIdx.x;
    const int lane = tid & 31;
    const int warp = tid >> 5;             // 0..3
    const int wm = warp >> 1;              // 0..1  (64-row half)
    const int wn = warp & 1;               // 0..1  (64-col half)

    // decode blockIdx -> (I, c): octet o of I, chunks c = o..7
    int t = blockIdx.x, o = 0;
    for (;;) { int n = (8 - o) * 8; if (t < n) break; t -= n; ++o; }
    const int c  = o + (t >> 3);
    const int I  = 8 * o + (t & 7);
    const int J0 = max(8 * c, I);
    const int L  = 8 * c + 8 - J0;         // strip length (1..8)
    const int rowBase = I * 128;

    const char* __restrict__ Xb = reinterpret_cast<const char*>(g_Xh);

    // cooperative 32KB tile load (128 rows x 256B), 128 threads
    auto loadTile = [&](uint32_t dst, int gRow) {
        #pragma unroll
        for (int i = 0; i < 16; ++i) {
            int f = tid + i * 128;          // 0..2047 16B-chunks
            int r = f >> 4, cc = (f & 15) << 4;
            cp16(dst + r * SROWB + cc, Xb + (size_t)(gRow + r) * 256 + cc);
        }
    };

    loadTile(sb + SM_A, rowBase);
    loadTile(sb + SM_B0, J0 * 128);
    CP_COMMIT();

    const uint32_t aBase = sb + SM_A + (uint32_t)(wm * 64 + (lane & 15)) * SROWB + ((lane >> 4) << 4);
    const uint32_t bOff  = (uint32_t)(wn * 64 + (lane & 15)) * SROWB + ((lane >> 4) << 4);

    float rs32[8] = {0.f};                 // strip row sums (fp32), [mm*2+g]
    float* colred = reinterpret_cast<float*>(smem + SM_RED);   // [2][128]

    for (int k = 0; k < L; ++k) {
        const int J = J0 + k;
        CP_WAIT0();
        __syncthreads();   // B(k) resident; prev tile's colred reads done

        if (k + 1 < L) {
            loadTile(sb + (((k + 1) & 1) ? SM_B1 : SM_B0), (J + 1) * 128);
            CP_COMMIT();
        }

        const uint32_t bBase = sb + ((k & 1) ? SM_B1 : SM_B0) + bOff;

        uint32_t acc[4][8][2];             // f16x2 accumulators [m16-group][n8][reg]
        #pragma unroll
        for (int m = 0; m < 4; ++m)
            #pragma unroll
            for (int n = 0; n < 8; ++n) { acc[m][n][0] = 0u; acc[m][n][1] = 0u; }

        #pragma unroll
        for (int ks = 0; ks < 8; ++ks) {
            uint32_t a[4][4], b[4][4];
            #pragma unroll
            for (int m = 0; m < 4; ++m)
                ldsm4(a[m], aBase + m * (16 * SROWB) + ks * 32);
            #pragma unroll
            for (int n4 = 0; n4 < 4; ++n4)
                ldsm4(b[n4], bBase + n4 * (16 * SROWB) + ks * 32);
            #pragma unroll
            for (int m = 0; m < 4; ++m)
                #pragma unroll
                for (int n4 = 0; n4 < 4; ++n4) {
                    mma16816h(acc[m][n4 * 2 + 0], a[m], b[n4][0], b[n4][2]);
                    mma16816h(acc[m][n4 * 2 + 1], a[m], b[n4][1], b[n4][3]);
                }
        }

        // epilogue: packed e = ex2(acc); row sums + column sums
        uint32_t cs[8];
        #pragma unroll
        for (int n = 0; n < 8; ++n) cs[n] = 0u;

        #pragma unroll
        for (int m = 0; m < 4; ++m) {
            uint32_t rsp[2] = {0u, 0u};
            #pragma unroll
            for (int n = 0; n < 8; ++n) {
                uint32_t e0 = hex2(acc[m][n][0]);
                uint32_t e1 = hex2(acc[m][n][1]);
                rsp[0] = hadd2(rsp[0], e0);
                rsp[1] = hadd2(rsp[1], e1);
                cs[n] = hadd2(cs[n], hadd2(e0, e1));
            }
            #pragma unroll
            for (int g = 0; g < 2; ++g) {
                float2 f = h2f(rsp[g]);
                rs32[m * 2 + g] += f.x + f.y;
            }
        }

        if (J != I) {
            // column sums: combine the 8 row-groups within each warp (packed)
            #pragma unroll
            for (int n = 0; n < 8; ++n) {
                cs[n] = hadd2(cs[n], __shfl_xor_sync(0xffffffffu, cs[n], 4));
                cs[n] = hadd2(cs[n], __shfl_xor_sync(0xffffffffu, cs[n], 8));
                cs[n] = hadd2(cs[n], __shfl_xor_sync(0xffffffffu, cs[n], 16));
            }
            if (lane < 4) {
                #pragma unroll
                for (int n = 0; n < 8; ++n) {
                    int cc = wn * 64 + (n >> 1) * 16 + (n & 1) * 8 + lane * 2;
                    float2 f = h2f(cs[n]);
                    *reinterpret_cast<float2*>(&colred[wm * 128 + cc]) = f;
                }
            }
            __syncthreads();
            // combine the 2 wm-halves; all 128 threads
            {
                float ct = colred[tid] + colred[128 + tid];
                g_part[8 + I][J * 128 + tid] = ct;
            }
        } else {
            __syncthreads();   // keep barrier count uniform
        }
    }

    // strip row sums: lanes sharing a row (lane&3), then combine 2 wn-halves
    #pragma unroll
    for (int u = 0; u < 8; ++u) {
        rs32[u] += __shfl_xor_sync(0xffffffffu, rs32[u], 1);
        rs32[u] += __shfl_xor_sync(0xffffffffu, rs32[u], 2);
    }
    float* rowred = reinterpret_cast<float*>(smem + SM_RED);   // [2][128]
    __syncthreads();
    if ((lane & 3) == 0) {
        #pragma unroll
        for (int u = 0; u < 8; ++u) {
            int r = wm * 64 + (u >> 1) * 16 + (u & 1) * 8 + (lane >> 2);
            rowred[wn * 128 + r] = rs32[u];
        }
    }
    __syncthreads();
    g_part[c][rowBase + tid] = rowred[tid] + rowred[128 + tid];
}

// ---------------------------------------------------------------------------
// 3) Fused finalize + reduce. 32 blocks x 256 threads, one row per thread.
// ---------------------------------------------------------------------------
__global__ void __launch_bounds__(256) finalize_reduce_kernel(
        const float* __restrict__ E, const int* __restrict__ labels,
        float* __restrict__ out) {
    const int i = blockIdx.x * 256 + threadIdx.x;

    float R = 0.f;
    #pragma unroll 8
    for (int s = 0; s < NSLOT; ++s) R += g_part[s][i];

    int pos = (i < TWO_B / 2) ? (i + TWO_B / 2) : (i - TWO_B / 2);
    int a = min(i, pos), b = max(i, pos);
    int l = labels[i];
    int j = l + (l >= a ? 1 : 0);
    j += (j >= b ? 1 : 0);

    // exact fp32 picked logit from raw E + inverse norms
    const float* ei = E + (size_t)i * DIM;
    const float* ej = E + (size_t)j * DIM;
    float dq = 0.f;
    #pragma unroll
    for (int k = 0; k < DIM; k += 4) {
        float4 vi = *reinterpret_cast<const float4*>(&ei[k]);
        float4 vj = *reinterpret_cast<const float4*>(&ej[k]);
        dq += vi.x * vj.x + vi.y * vj.y + vi.z * vj.z + vi.w * vj.w;
    }
    float q = 2.0f * dq * g_inorm[i] * g_inorm[j];

    // fp16-consistent diagonal + positive-pair terms (scaled: acc == ex2 arg)
    float dii = 0.f, dpp = 0.f;
    const __half* hi = g_Xh + (size_t)i   * DIM;
    const __half* hp = g_Xh + (size_t)pos * DIM;
    #pragma unroll
    for (int k = 0; k < DIM; k += 2) {
        float2 a2 = __half22float2(*reinterpret_cast<const __half2*>(&hi[k]));
        float2 b2 = __half22float2(*reinterpret_cast<const __half2*>(&hp[k]));
        dii += a2.x * a2.x + a2.y * a2.y;
        dpp += a2.x * b2.x + a2.y * b2.y;
    }

    float masked = R - ex2f(dii) - ex2f(dpp);
    float loss = logf(masked) - q;

    // block reduce (deterministic) + last-block combine
    __shared__ float sm[256];
    __shared__ bool isLast;
    sm[threadIdx.x] = loss;
    __syncthreads();
    #pragma unroll
    for (int off = 128; off > 0; off >>= 1) {
        if (threadIdx.x < off) sm[threadIdx.x] += sm[threadIdx.x + off];
        __syncthreads();
    }
    if (threadIdx.x == 0) {
        g_bpart[blockIdx.x] = sm[0];
        __threadfence();
        int cdone = atomicAdd(&g_count, 1);
        isLast = (cdone == NFBLK - 1);
    }
    __syncthreads();
    if (isLast && threadIdx.x == 0) {
        float s = 0.f;
        #pragma unroll
        for (int bb = 0; bb < NFBLK; ++bb) s += g_bpart[bb];
        out[0] = s / (float)TWO_B;
        g_count = 0;                      // reset for next graph replay
    }
}

// ---------------------------------------------------------------------------
extern "C" void kernel_launch(void* const* d_in, const int* in_sizes, int n_in,
                              void* d_out, int out_size) {
    const float* E      = (const float*)d_in[0];
    const int*   labels = (const int*)d_in[1];
    float* out = (float*)d_out;

    cudaFuncSetAttribute(gemm_sym_kernel,
                         cudaFuncAttributeMaxDynamicSharedMemorySize, SM_TOT);

    normalize_kernel<<<TWO_B / 8, 256>>>(E);
    gemm_sym_kernel<<<NCTA, 128, SM_TOT>>>();
    finalize_reduce_kernel<<<NFBLK, 256>>>(E, labels, out);
}

// round 14
// speedup vs baseline: 1.2705x; 1.0024x over previous
#include <cuda_runtime.h>
#include <cuda_fp16.h>
#include <math.h>
#include <cstdint>

// NTXent loss, 2B = 8192, D = 128.
// Symmetric fp16 HMMA GEMM (f16 acc), strip-mined upper-triangle blocks.
// 128 threads/CTA, warp tile 64x64 (2x2 warps).
// Inputs pre-scaled by sqrt(2*log2(e)) so acc == ex2 argument.
// 3 launches chained with Programmatic Dependent Launch (PDL) to overlap
// launch latency and prologues with predecessor tails.

#define TWO_B   8192
#define DIM     128
#define NBLK    64
#define NCTA    288           // sum over octets o: (8-o)*8
#define NSLOT   72            // 8 row-sum slots + 64 col-sum slots
#define NFBLK   32            // finalize blocks

__device__ __half g_Xh[TWO_B * DIM];            // normalized*sqrt(C2) fp16 (MMA)
__device__ float  g_inorm[TWO_B];               // 1/||e_i||
__device__ float  g_part[NSLOT][TWO_B];         // [slot][row] partials (unused stay 0)
__device__ float  g_bpart[NFBLK];               // per-block loss partials
__device__ int    g_count;                      // last-block counter (self-resetting)

// C2 = 2*log2(e); SQC2 = sqrt(C2)
#define SQC2 1.6986435838704467f

// ---------------------------------------------------------------------------
// helpers
// ---------------------------------------------------------------------------
__device__ __forceinline__ uint32_t smem_u32(const void* p) {
    uint32_t a;
    asm("{ .reg .u64 t; cvta.to.shared.u64 t, %1; cvt.u32.u64 %0, t; }" : "=r"(a) : "l"(p));
    return a;
}
__device__ __forceinline__ void cp16(uint32_t saddr, const void* g) {
    asm volatile("cp.async.cg.shared.global [%0], [%1], 16;" :: "r"(saddr), "l"(g));
}
#define CP_COMMIT() asm volatile("cp.async.commit_group;" ::: "memory")
#define CP_WAIT0()  asm volatile("cp.async.wait_group 0;" ::: "memory")

__device__ __forceinline__ void ldsm4(uint32_t* r, uint32_t addr) {
    asm volatile("ldmatrix.sync.aligned.m8n8.x4.shared.b16 {%0,%1,%2,%3}, [%4];"
                 : "=r"(r[0]), "=r"(r[1]), "=r"(r[2]), "=r"(r[3]) : "r"(addr));
}
__device__ __forceinline__ void mma16816h(uint32_t* d, const uint32_t* a, uint32_t b0, uint32_t b1) {
    asm volatile("mma.sync.aligned.m16n8k16.row.col.f16.f16.f16.f16 "
                 "{%0,%1}, {%2,%3,%4,%5}, {%6,%7}, {%0,%1};"
                 : "+r"(d[0]), "+r"(d[1])
                 : "r"(a[0]), "r"(a[1]), "r"(a[2]), "r"(a[3]), "r"(b0), "r"(b1));
}
__device__ __forceinline__ uint32_t hex2(uint32_t x) {
    uint32_t y; asm("ex2.approx.f16x2 %0, %1;" : "=r"(y) : "r"(x)); return y;
}
__device__ __forceinline__ uint32_t hadd2(uint32_t a, uint32_t b) {
    uint32_t y; asm("add.rn.f16x2 %0, %1, %2;" : "=r"(y) : "r"(a), "r"(b)); return y;
}
__device__ __forceinline__ float2 h2f(uint32_t r) {
    __half2 h = *reinterpret_cast<__half2*>(&r);
    return __half22float2(h);
}
__device__ __forceinline__ float ex2f(float x) {
    float y; asm("ex2.approx.ftz.f32 %0, %1;" : "=f"(y) : "f"(x)); return y;
}
__device__ __forceinline__ void pdl_trigger() {
    asm volatile("griddepcontrol.launch_dependents;" ::: "memory");
}
__device__ __forceinline__ void pdl_wait() {
    asm volatile("griddepcontrol.wait;" ::: "memory");
}

// ---------------------------------------------------------------------------
// 1) Row-normalize -> scaled fp16 + inverse norms. One warp per row.
// ---------------------------------------------------------------------------
__global__ void __launch_bounds__(256) normalize_kernel(const float* __restrict__ E) {
    int warp = threadIdx.x >> 5, lane = threadIdx.x & 31;
    int row = blockIdx.x * 8 + warp;
    const float4 v = *reinterpret_cast<const float4*>(&E[row * DIM + lane * 4]);
    float ss = v.x * v.x + v.y * v.y + v.z * v.z + v.w * v.w;
    #pragma unroll
    for (int o = 16; o > 0; o >>= 1) ss += __shfl_xor_sync(0xffffffffu, ss, o);
    float inv = rsqrtf(fmaxf(ss, 1e-24f));
    if (lane == 0) g_inorm[row] = inv;
    float s = inv * SQC2;
    __half2 h0 = __float22half2_rn(make_float2(v.x * s, v.y * s));
    __half2 h1 = __float22half2_rn(make_float2(v.z * s, v.w * s));
    uint2 pk = { *reinterpret_cast<uint32_t*>(&h0), *reinterpret_cast<uint32_t*>(&h1) };
    *reinterpret_cast<uint2*>(&g_Xh[row * DIM + lane * 4]) = pk;
    pdl_trigger();
}

// ---------------------------------------------------------------------------
// 2) Strip-mined symmetric HMMA GEMM (f16 acc) + exp row/col sums.
//    128 threads = 4 warps (wm 0..1 x wn 0..1); warp tile 64x64; K=128.
// ---------------------------------------------------------------------------
#define SROWB   272                        // smem row stride (17*16 B)
#define TILE_B  (128 * SROWB)              // 34816
#define SM_A    0
#define SM_B0   TILE_B
#define SM_B1   (2 * TILE_B)
#define SM_RED  (3 * TILE_B)               // colred[2][128] / rowred[2][128]
#define SM_TOT  (SM_RED + 2 * 128 * 4)

__global__ void __launch_bounds__(128, 2) gemm_sym_kernel() {
    extern __shared__ __align__(16) char smem[];
    const uint32_t sb = smem_u32(smem);
    const int tid  = threadIdx.x;
    const int lane = tid & 31;
    const int warp = tid >> 5;             // 0..3
    const int wm = warp >> 1;              // 0..1  (64-row half)
    const int wn = warp & 1;               // 0..1  (64-col half)

    // decode blockIdx -> (I, c): octet o of I, chunks c = o..7  (pre-sync work)
    int t = blockIdx.x, o = 0;
    for (;;) { int n = (8 - o) * 8; if (t < n) break; t -= n; ++o; }
    const int c  = o + (t >> 3);
    const int I  = 8 * o + (t & 7);
    const int J0 = max(8 * c, I);
    const int L  = 8 * c + 8 - J0;         // strip length (1..8)
    const int rowBase = I * 128;

    const char* __restrict__ Xb = reinterpret_cast<const char*>(g_Xh);

    // cooperative 32KB tile load (128 rows x 256B), 128 threads
    auto loadTile = [&](uint32_t dst, int gRow) {
        #pragma unroll
        for (int i = 0; i < 16; ++i) {
            int f = tid + i * 128;          // 0..2047 16B-chunks
            int r = f >> 4, cc = (f & 15) << 4;
            cp16(dst + r * SROWB + cc, Xb + (size_t)(gRow + r) * 256 + cc);
        }
    };

    pdl_wait();                             // g_Xh ready (normalize complete)

    loadTile(sb + SM_A, rowBase);
    loadTile(sb + SM_B0, J0 * 128);
    CP_COMMIT();

    const uint32_t aBase = sb + SM_A + (uint32_t)(wm * 64 + (lane & 15)) * SROWB + ((lane >> 4) << 4);
    const uint32_t bOff  = (uint32_t)(wn * 64 + (lane & 15)) * SROWB + ((lane >> 4) << 4);

    float rs32[8] = {0.f};                 // strip row sums (fp32), [m*2+g]
    float* colred = reinterpret_cast<float*>(smem + SM_RED);   // [2][128]

    for (int k = 0; k < L; ++k) {
        const int J = J0 + k;
        CP_WAIT0();
        __syncthreads();   // B(k) resident; prev tile's colred reads done

        if (k + 1 < L) {
            loadTile(sb + (((k + 1) & 1) ? SM_B1 : SM_B0), (J + 1) * 128);
            CP_COMMIT();
        }

        const uint32_t bBase = sb + ((k & 1) ? SM_B1 : SM_B0) + bOff;

        uint32_t acc[4][8][2];             // f16x2 accumulators
        #pragma unroll
        for (int m = 0; m < 4; ++m)
            #pragma unroll
            for (int n = 0; n < 8; ++n) { acc[m][n][0] = 0u; acc[m][n][1] = 0u; }

        #pragma unroll
        for (int ks = 0; ks < 8; ++ks) {
            uint32_t a[4][4], b[4][4];
            #pragma unroll
            for (int m = 0; m < 4; ++m)
                ldsm4(a[m], aBase + m * (16 * SROWB) + ks * 32);
            #pragma unroll
            for (int n4 = 0; n4 < 4; ++n4)
                ldsm4(b[n4], bBase + n4 * (16 * SROWB) + ks * 32);
            #pragma unroll
            for (int m = 0; m < 4; ++m)
                #pragma unroll
                for (int n4 = 0; n4 < 4; ++n4) {
                    mma16816h(acc[m][n4 * 2 + 0], a[m], b[n4][0], b[n4][2]);
                    mma16816h(acc[m][n4 * 2 + 1], a[m], b[n4][1], b[n4][3]);
                }
        }

        // epilogue: packed e = ex2(acc); row sums + column sums
        uint32_t cs[8];
        #pragma unroll
        for (int n = 0; n < 8; ++n) cs[n] = 0u;

        #pragma unroll
        for (int m = 0; m < 4; ++m) {
            uint32_t rsp[2] = {0u, 0u};
            #pragma unroll
            for (int n = 0; n < 8; ++n) {
                uint32_t e0 = hex2(acc[m][n][0]);
                uint32_t e1 = hex2(acc[m][n][1]);
                rsp[0] = hadd2(rsp[0], e0);
                rsp[1] = hadd2(rsp[1], e1);
                cs[n] = hadd2(cs[n], hadd2(e0, e1));
            }
            #pragma unroll
            for (int g = 0; g < 2; ++g) {
                float2 f = h2f(rsp[g]);
                rs32[m * 2 + g] += f.x + f.y;
            }
        }

        if (J != I) {
            #pragma unroll
            for (int n = 0; n < 8; ++n) {
                cs[n] = hadd2(cs[n], __shfl_xor_sync(0xffffffffu, cs[n], 4));
                cs[n] = hadd2(cs[n], __shfl_xor_sync(0xffffffffu, cs[n], 8));
                cs[n] = hadd2(cs[n], __shfl_xor_sync(0xffffffffu, cs[n], 16));
            }
            if (lane < 4) {
                #pragma unroll
                for (int n = 0; n < 8; ++n) {
                    int cc = wn * 64 + (n >> 1) * 16 + (n & 1) * 8 + lane * 2;
                    float2 f = h2f(cs[n]);
                    *reinterpret_cast<float2*>(&colred[wm * 128 + cc]) = f;
                }
            }
            __syncthreads();
            {
                float ct = colred[tid] + colred[128 + tid];
                g_part[8 + I][J * 128 + tid] = ct;
            }
        } else {
            __syncthreads();   // keep barrier count uniform
        }
    }

    // strip row sums
    #pragma unroll
    for (int u = 0; u < 8; ++u) {
        rs32[u] += __shfl_xor_sync(0xffffffffu, rs32[u], 1);
        rs32[u] += __shfl_xor_sync(0xffffffffu, rs32[u], 2);
    }
    float* rowred = reinterpret_cast<float*>(smem + SM_RED);   // [2][128]
    __syncthreads();
    if ((lane & 3) == 0) {
        #pragma unroll
        for (int u = 0; u < 8; ++u) {
            int r = wm * 64 + (u >> 1) * 16 + (u & 1) * 8 + (lane >> 2);
            rowred[wn * 128 + r] = rs32[u];
        }
    }
    __syncthreads();
    g_part[c][rowBase + tid] = rowred[tid] + rowred[128 + tid];
    pdl_trigger();
}

// ---------------------------------------------------------------------------
// 3) Fused finalize + reduce. 32 blocks x 256 threads, one row per thread.
//    All g_part-independent work happens BEFORE the PDL wait.
// ---------------------------------------------------------------------------
__global__ void __launch_bounds__(256) finalize_reduce_kernel(
        const float* __restrict__ E, const int* __restrict__ labels,
        float* __restrict__ out) {
    const int i = blockIdx.x * 256 + threadIdx.x;

    int pos = (i < TWO_B / 2) ? (i + TWO_B / 2) : (i - TWO_B / 2);
    int a = min(i, pos), b = max(i, pos);
    int l = labels[i];
    int j = l + (l >= a ? 1 : 0);
    j += (j >= b ? 1 : 0);

    // exact fp32 picked logit from raw E + inverse norms (independent of g_part;
    // g_inorm/g_Xh were completed by normalize, ordered before this launch)
    const float* ei = E + (size_t)i * DIM;
    const float* ej = E + (size_t)j * DIM;
    float dq = 0.f;
    #pragma unroll
    for (int k = 0; k < DIM; k += 4) {
        float4 vi = *reinterpret_cast<const float4*>(&ei[k]);
        float4 vj = *reinterpret_cast<const float4*>(&ej[k]);
        dq += vi.x * vj.x + vi.y * vj.y + vi.z * vj.z + vi.w * vj.w;
    }
    float q = 2.0f * dq * g_inorm[i] * g_inorm[j];

    // fp16-consistent diagonal + positive-pair terms (scaled: acc == ex2 arg)
    float dii = 0.f, dpp = 0.f;
    const __half* hi = g_Xh + (size_t)i   * DIM;
    const __half* hp = g_Xh + (size_t)pos * DIM;
    #pragma unroll
    for (int k = 0; k < DIM; k += 2) {
        float2 a2 = __half22float2(*reinterpret_cast<const __half2*>(&hi[k]));
        float2 b2 = __half22float2(*reinterpret_cast<const __half2*>(&hp[k]));
        dii += a2.x * a2.x + a2.y * a2.y;
        dpp += a2.x * b2.x + a2.y * b2.y;
    }
    float sub = ex2f(dii) + ex2f(dpp);

    pdl_wait();                             // g_part ready (gemm complete)

    float R = 0.f;
    #pragma unroll 8
    for (int s = 0; s < NSLOT; ++s) R += g_part[s][i];

    float loss = logf(R - sub) - q;

    // block reduce (deterministic) + last-block combine
    __shared__ float sm[256];
    __shared__ bool isLast;
    sm[threadIdx.x] = loss;
    __syncthreads();
    #pragma unroll
    for (int off = 128; off > 0; off >>= 1) {
        if (threadIdx.x < off) sm[threadIdx.x] += sm[threadIdx.x + off];
        __syncthreads();
    }
    if (threadIdx.x == 0) {
        g_bpart[blockIdx.x] = sm[0];
        __threadfence();
        int cdone = atomicAdd(&g_count, 1);
        isLast = (cdone == NFBLK - 1);
    }
    __syncthreads();
    if (isLast && threadIdx.x == 0) {
        float s = 0.f;
        #pragma unroll
        for (int bb = 0; bb < NFBLK; ++bb) s += g_bpart[bb];
        out[0] = s / (float)TWO_B;
        g_count = 0;                      // reset for next graph replay
    }
}

// ---------------------------------------------------------------------------
extern "C" void kernel_launch(void* const* d_in, const int* in_sizes, int n_in,
                              void* d_out, int out_size) {
    const float* E      = (const float*)d_in[0];
    const int*   labels = (const int*)d_in[1];
    float* out = (float*)d_out;

    static bool attrSet = false;
    if (!attrSet) {
        cudaFuncSetAttribute(gemm_sym_kernel,
                             cudaFuncAttributeMaxDynamicSharedMemorySize, SM_TOT);
        attrSet = true;
    }

    // 1) normalize (plain launch)
    normalize_kernel<<<TWO_B / 8, 256>>>(E);

    // 2) gemm with PDL on normalize
    {
        cudaLaunchAttribute attr[1];
        attr[0].id = cudaLaunchAttributeProgrammaticStreamSerialization;
        attr[0].val.programmaticStreamSerializationAllowed = 1;
        cudaLaunchConfig_t cfg = {};
        cfg.gridDim = dim3(NCTA, 1, 1);
        cfg.blockDim = dim3(128, 1, 1);
        cfg.dynamicSmemBytes = SM_TOT;
        cfg.stream = 0;
        cfg.attrs = attr;
        cfg.numAttrs = 1;
        cudaLaunchKernelEx(&cfg, gemm_sym_kernel);
    }

    // 3) finalize with PDL on gemm
    {
        cudaLaunchAttribute attr[1];
        attr[0].id = cudaLaunchAttributeProgrammaticStreamSerialization;
        attr[0].val.programmaticStreamSerializationAllowed = 1;
        cudaLaunchConfig_t cfg = {};
        cfg.gridDim = dim3(NFBLK, 1, 1);
        cfg.blockDim = dim3(256, 1, 1);
        cfg.dynamicSmemBytes = 0;
        cfg.stream = 0;
        cfg.attrs = attr;
        cfg.numAttrs = 1;
        cudaLaunchKernelEx(&cfg, finalize_reduce_kernel, E, labels, out);
    }
}

// round 16
// speedup vs baseline: 1.2791x; 1.0068x over previous
#include <cuda_runtime.h>
#include <cuda_fp16.h>
#include <math.h>
#include <cstdint>

// NTXent loss, 2B = 8192, D = 128.
// Symmetric fp16 HMMA GEMM (f16 acc), strip-mined upper-triangle blocks.
// 128 threads/CTA, warp tile 64x64 (2x2 warps).
// R15: phase-staggered co-resident CTAs + ks-level fragment double-buffering.
// Inputs pre-scaled by sqrt(2*log2(e)) so acc == ex2 argument.
// 3 launches chained with PDL.

#define TWO_B   8192
#define DIM     128
#define NBLK    64
#define NCTA    288           // sum over octets o: (8-o)*8
#define NSLOT   72            // 8 row-sum slots + 64 col-sum slots
#define NFBLK   32            // finalize blocks

__device__ __half g_Xh[TWO_B * DIM];            // normalized*sqrt(C2) fp16 (MMA)
__device__ float  g_inorm[TWO_B];               // 1/||e_i||
__device__ float  g_part[NSLOT][TWO_B];         // [slot][row] partials (unused stay 0)
__device__ float  g_bpart[NFBLK];               // per-block loss partials
__device__ int    g_count;                      // last-block counter (self-resetting)

// C2 = 2*log2(e); SQC2 = sqrt(C2)
#define SQC2 1.6986435838704467f

// ---------------------------------------------------------------------------
// helpers
// ---------------------------------------------------------------------------
__device__ __forceinline__ uint32_t smem_u32(const void* p) {
    uint32_t a;
    asm("{ .reg .u64 t; cvta.to.shared.u64 t, %1; cvt.u32.u64 %0, t; }" : "=r"(a) : "l"(p));
    return a;
}
__device__ __forceinline__ void cp16(uint32_t saddr, const void* g) {
    asm volatile("cp.async.cg.shared.global [%0], [%1], 16;" :: "r"(saddr), "l"(g));
}
#define CP_COMMIT() asm volatile("cp.async.commit_group;" ::: "memory")
#define CP_WAIT0()  asm volatile("cp.async.wait_group 0;" ::: "memory")

__device__ __forceinline__ void ldsm4(uint32_t* r, uint32_t addr) {
    asm volatile("ldmatrix.sync.aligned.m8n8.x4.shared.b16 {%0,%1,%2,%3}, [%4];"
                 : "=r"(r[0]), "=r"(r[1]), "=r"(r[2]), "=r"(r[3]) : "r"(addr));
}
__device__ __forceinline__ void mma16816h(uint32_t* d, const uint32_t* a, uint32_t b0, uint32_t b1) {
    asm volatile("mma.sync.aligned.m16n8k16.row.col.f16.f16.f16.f16 "
                 "{%0,%1}, {%2,%3,%4,%5}, {%6,%7}, {%0,%1};"
                 : "+r"(d[0]), "+r"(d[1])
                 : "r"(a[0]), "r"(a[1]), "r"(a[2]), "r"(a[3]), "r"(b0), "r"(b1));
}
__device__ __forceinline__ uint32_t hex2(uint32_t x) {
    uint32_t y; asm("ex2.approx.f16x2 %0, %1;" : "=r"(y) : "r"(x)); return y;
}
__device__ __forceinline__ uint32_t hadd2(uint32_t a, uint32_t b) {
    uint32_t y; asm("add.rn.f16x2 %0, %1, %2;" : "=r"(y) : "r"(a), "r"(b)); return y;
}
__device__ __forceinline__ float2 h2f(uint32_t r) {
    __half2 h = *reinterpret_cast<__half2*>(&r);
    return __half22float2(h);
}
__device__ __forceinline__ float ex2f(float x) {
    float y; asm("ex2.approx.ftz.f32 %0, %1;" : "=f"(y) : "f"(x)); return y;
}
__device__ __forceinline__ void pdl_trigger() {
    asm volatile("griddepcontrol.launch_dependents;" ::: "memory");
}
__device__ __forceinline__ void pdl_wait() {
    asm volatile("griddepcontrol.wait;" ::: "memory");
}

// ---------------------------------------------------------------------------
// 1) Row-normalize -> scaled fp16 + inverse norms. One warp per row.
// ---------------------------------------------------------------------------
__global__ void __launch_bounds__(256) normalize_kernel(const float* __restrict__ E) {
    int warp = threadIdx.x >> 5, lane = threadIdx.x & 31;
    int row = blockIdx.x * 8 + warp;
    const float4 v = *reinterpret_cast<const float4*>(&E[row * DIM + lane * 4]);
    float ss = v.x * v.x + v.y * v.y + v.z * v.z + v.w * v.w;
    #pragma unroll
    for (int o = 16; o > 0; o >>= 1) ss += __shfl_xor_sync(0xffffffffu, ss, o);
    float inv = rsqrtf(fmaxf(ss, 1e-24f));
    if (lane == 0) g_inorm[row] = inv;
    float s = inv * SQC2;
    __half2 h0 = __float22half2_rn(make_float2(v.x * s, v.y * s));
    __half2 h1 = __float22half2_rn(make_float2(v.z * s, v.w * s));
    uint2 pk = { *reinterpret_cast<uint32_t*>(&h0), *reinterpret_cast<uint32_t*>(&h1) };
    *reinterpret_cast<uint2*>(&g_Xh[row * DIM + lane * 4]) = pk;
    pdl_trigger();
}

// ---------------------------------------------------------------------------
// 2) Strip-mined symmetric HMMA GEMM (f16 acc) + exp row/col sums.
//    128 threads = 4 warps (wm 0..1 x wn 0..1); warp tile 64x64; K=128.
// ---------------------------------------------------------------------------
#define SROWB   272                        // smem row stride (17*16 B)
#define TILE_B  (128 * SROWB)              // 34816
#define SM_A    0
#define SM_B0   TILE_B
#define SM_B1   (2 * TILE_B)
#define SM_RED  (3 * TILE_B)               // colred[2][128] / rowred[2][128]
#define SM_TOT  (SM_RED + 2 * 128 * 4)

__global__ void __launch_bounds__(128, 2) gemm_sym_kernel() {
    extern __shared__ __align__(16) char smem[];
    const uint32_t sb = smem_u32(smem);
    const int tid  = threadIdx.x;
    const int lane = tid & 31;
    const int warp = tid >> 5;             // 0..3
    const int wm = warp >> 1;              // 0..1  (64-row half)
    const int wn = warp & 1;               // 0..1  (64-col half)

    // decode blockIdx -> (I, c): octet o of I, chunks c = o..7  (pre-sync work)
    int t = blockIdx.x, o = 0;
    for (;;) { int n = (8 - o) * 8; if (t < n) break; t -= n; ++o; }
    const int c  = o + (t >> 3);
    const int I  = 8 * o + (t & 7);
    const int J0 = max(8 * c, I);
    const int L  = 8 * c + 8 - J0;         // strip length (1..8)
    const int rowBase = I * 128;

    const char* __restrict__ Xb = reinterpret_cast<const char*>(g_Xh);

    // cooperative 32KB tile load (128 rows x 256B), 128 threads
    auto loadTile = [&](uint32_t dst, int gRow) {
        #pragma unroll
        for (int i = 0; i < 16; ++i) {
            int f = tid + i * 128;          // 0..2047 16B-chunks
            int r = f >> 4, cc = (f & 15) << 4;
            cp16(dst + r * SROWB + cc, Xb + (size_t)(gRow + r) * 256 + cc);
        }
    };

    pdl_wait();                             // g_Xh ready (normalize complete)

    loadTile(sb + SM_A, rowBase);
    loadTile(sb + SM_B0, J0 * 128);
    CP_COMMIT();

    // phase-stagger: second-slot co-resident CTAs offset by ~half a tile period
    if (blockIdx.x >= 148) __nanosleep(800);

    const uint32_t aBase = sb + SM_A + (uint32_t)(wm * 64 + (lane & 15)) * SROWB + ((lane >> 4) << 4);
    const uint32_t bOff  = (uint32_t)(wn * 64 + (lane & 15)) * SROWB + ((lane >> 4) << 4);

    float rs32[8] = {0.f};                 // strip row sums (fp32), [m*2+g]
    float* colred = reinterpret_cast<float*>(smem + SM_RED);   // [2][128]

    for (int k = 0; k < L; ++k) {
        const int J = J0 + k;
        CP_WAIT0();
        __syncthreads();   // B(k) resident; prev tile's colred reads done

        if (k + 1 < L) {
            loadTile(sb + (((k + 1) & 1) ? SM_B1 : SM_B0), (J + 1) * 128);
            CP_COMMIT();
        }

        const uint32_t bBase = sb + ((k & 1) ? SM_B1 : SM_B0) + bOff;

        uint32_t acc[4][8][2];             // f16x2 accumulators
        #pragma unroll
        for (int m = 0; m < 4; ++m)
            #pragma unroll
            for (int n = 0; n < 8; ++n) { acc[m][n][0] = 0u; acc[m][n][1] = 0u; }

        // ks-level fragment double-buffering: load ks+1 before issuing ks MMAs
        uint32_t af[2][4][4], bf[2][4][4];
        #pragma unroll
        for (int m = 0; m < 4; ++m)
            ldsm4(af[0][m], aBase + m * (16 * SROWB));
        #pragma unroll
        for (int n4 = 0; n4 < 4; ++n4)
            ldsm4(bf[0][n4], bBase + n4 * (16 * SROWB));

        #pragma unroll
        for (int ks = 0; ks < 8; ++ks) {
            const int cur = ks & 1, nxt = cur ^ 1;
            if (ks < 7) {
                #pragma unroll
                for (int m = 0; m < 4; ++m)
                    ldsm4(af[nxt][m], aBase + m * (16 * SROWB) + (ks + 1) * 32);
                #pragma unroll
                for (int n4 = 0; n4 < 4; ++n4)
                    ldsm4(bf[nxt][n4], bBase + n4 * (16 * SROWB) + (ks + 1) * 32);
            }
            #pragma unroll
            for (int m = 0; m < 4; ++m)
                #pragma unroll
                for (int n4 = 0; n4 < 4; ++n4) {
                    mma16816h(acc[m][n4 * 2 + 0], af[cur][m], bf[cur][n4][0], bf[cur][n4][2]);
                    mma16816h(acc[m][n4 * 2 + 1], af[cur][m], bf[cur][n4][1], bf[cur][n4][3]);
                }
        }

        // epilogue: packed e = ex2(acc); row sums + column sums
        uint32_t cs[8];
        #pragma unroll
        for (int n = 0; n < 8; ++n) cs[n] = 0u;

        #pragma unroll
        for (int m = 0; m < 4; ++m) {
            uint32_t rsp[2] = {0u, 0u};
            #pragma unroll
            for (int n = 0; n < 8; ++n) {
                uint32_t e0 = hex2(acc[m][n][0]);
                uint32_t e1 = hex2(acc[m][n][1]);
                rsp[0] = hadd2(rsp[0], e0);
                rsp[1] = hadd2(rsp[1], e1);
                cs[n] = hadd2(cs[n], hadd2(e0, e1));
            }
            #pragma unroll
            for (int g = 0; g < 2; ++g) {
                float2 f = h2f(rsp[g]);
                rs32[m * 2 + g] += f.x + f.y;
            }
        }

        if (J != I) {
            #pragma unroll
            for (int n = 0; n < 8; ++n) {
                cs[n] = hadd2(cs[n], __shfl_xor_sync(0xffffffffu, cs[n], 4));
                cs[n] = hadd2(cs[n], __shfl_xor_sync(0xffffffffu, cs[n], 8));
                cs[n] = hadd2(cs[n], __shfl_xor_sync(0xffffffffu, cs[n], 16));
            }
            if (lane < 4) {
                #pragma unroll
                for (int n = 0; n < 8; ++n) {
                    int cc = wn * 64 + (n >> 1) * 16 + (n & 1) * 8 + lane * 2;
                    float2 f = h2f(cs[n]);
                    *reinterpret_cast<float2*>(&colred[wm * 128 + cc]) = f;
                }
            }
            __syncthreads();
            {
                float ct = colred[tid] + colred[128 + tid];
                g_part[8 + I][J * 128 + tid] = ct;
            }
        } else {
            __syncthreads();   // keep barrier count uniform
        }
    }

    // strip row sums
    #pragma unroll
    for (int u = 0; u < 8; ++u) {
        rs32[u] += __shfl_xor_sync(0xffffffffu, rs32[u], 1);
        rs32[u] += __shfl_xor_sync(0xffffffffu, rs32[u], 2);
    }
    float* rowred = reinterpret_cast<float*>(smem + SM_RED);   // [2][128]
    __syncthreads();
    if ((lane & 3) == 0) {
        #pragma unroll
        for (int u = 0; u < 8; ++u) {
            int r = wm * 64 + (u >> 1) * 16 + (u & 1) * 8 + (lane >> 2);
            rowred[wn * 128 + r] = rs32[u];
        }
    }
    __syncthreads();
    g_part[c][rowBase + tid] = rowred[tid] + rowred[128 + tid];
    pdl_trigger();
}

// ---------------------------------------------------------------------------
// 3) Fused finalize + reduce. 32 blocks x 256 threads, one row per thread.
//    All g_part-independent work happens BEFORE the PDL wait.
// ---------------------------------------------------------------------------
__global__ void __launch_bounds__(256) finalize_reduce_kernel(
        const float* __restrict__ E, const int* __restrict__ labels,
        float* __restrict__ out) {
    const int i = blockIdx.x * 256 + threadIdx.x;

    int pos = (i < TWO_B / 2) ? (i + TWO_B / 2) : (i - TWO_B / 2);
    int a = min(i, pos), b = max(i, pos);
    int l = labels[i];
    int j = l + (l >= a ? 1 : 0);
    j += (j >= b ? 1 : 0);

    // exact fp32 picked logit from raw E + inverse norms (independent of g_part)
    const float* ei = E + (size_t)i * DIM;
    const float* ej = E + (size_t)j * DIM;
    float dq = 0.f;
    #pragma unroll
    for (int k = 0; k < DIM; k += 4) {
        float4 vi = *reinterpret_cast<const float4*>(&ei[k]);
        float4 vj = *reinterpret_cast<const float4*>(&ej[k]);
        dq += vi.x * vj.x + vi.y * vj.y + vi.z * vj.z + vi.w * vj.w;
    }
    float q = 2.0f * dq * g_inorm[i] * g_inorm[j];

    // fp16-consistent diagonal + positive-pair terms (scaled: acc == ex2 arg)
    float dii = 0.f, dpp = 0.f;
    const __half* hi = g_Xh + (size_t)i   * DIM;
    const __half* hp = g_Xh + (size_t)pos * DIM;
    #pragma unroll
    for (int k = 0; k < DIM; k += 2) {
        float2 a2 = __half22float2(*reinterpret_cast<const __half2*>(&hi[k]));
        float2 b2 = __half22float2(*reinterpret_cast<const __half2*>(&hp[k]));
        dii += a2.x * a2.x + a2.y * a2.y;
        dpp += a2.x * b2.x + a2.y * b2.y;
    }
    float sub = ex2f(dii) + ex2f(dpp);

    pdl_wait();                             // g_part ready (gemm complete)

    float R = 0.f;
    #pragma unroll 8
    for (int s = 0; s < NSLOT; ++s) R += g_part[s][i];

    float loss = logf(R - sub) - q;

    // block reduce (deterministic) + last-block combine
    __shared__ float sm[256];
    __shared__ bool isLast;
    sm[threadIdx.x] = loss;
    __syncthreads();
    #pragma unroll
    for (int off = 128; off > 0; off >>= 1) {
        if (threadIdx.x < off) sm[threadIdx.x] += sm[threadIdx.x + off];
        __syncthreads();
    }
    if (threadIdx.x == 0) {
        g_bpart[blockIdx.x] = sm[0];
        __threadfence();
        int cdone = atomicAdd(&g_count, 1);
        isLast = (cdone == NFBLK - 1);
    }
    __syncthreads();
    if (isLast && threadIdx.x == 0) {
        float s = 0.f;
        #pragma unroll
        for (int bb = 0; bb < NFBLK; ++bb) s += g_bpart[bb];
        out[0] = s / (float)TWO_B;
        g_count = 0;                      // reset for next graph replay
    }
}

// ---------------------------------------------------------------------------
extern "C" void kernel_launch(void* const* d_in, const int* in_sizes, int n_in,
                              void* d_out, int out_size) {
    const float* E      = (const float*)d_in[0];
    const int*   labels = (const int*)d_in[1];
    float* out = (float*)d_out;

    static bool attrSet = false;
    if (!attrSet) {
        cudaFuncSetAttribute(gemm_sym_kernel,
                             cudaFuncAttributeMaxDynamicSharedMemorySize, SM_TOT);
        attrSet = true;
    }

    // 1) normalize (plain launch)
    normalize_kernel<<<TWO_B / 8, 256>>>(E);

    // 2) gemm with PDL on normalize
    {
        cudaLaunchAttribute attr[1];
        attr[0].id = cudaLaunchAttributeProgrammaticStreamSerialization;
        attr[0].val.programmaticStreamSerializationAllowed = 1;
        cudaLaunchConfig_t cfg = {};
        cfg.gridDim = dim3(NCTA, 1, 1);
        cfg.blockDim = dim3(128, 1, 1);
        cfg.dynamicSmemBytes = SM_TOT;
        cfg.stream = 0;
        cfg.attrs = attr;
        cfg.numAttrs = 1;
        cudaLaunchKernelEx(&cfg, gemm_sym_kernel);
    }

    // 3) finalize with PDL on gemm
    {
        cudaLaunchAttribute attr[1];
        attr[0].id = cudaLaunchAttributeProgrammaticStreamSerialization;
        attr[0].val.programmaticStreamSerializationAllowed = 1;
        cudaLaunchConfig_t cfg = {};
        cfg.gridDim = dim3(NFBLK, 1, 1);
        cfg.blockDim = dim3(256, 1, 1);
        cfg.dynamicSmemBytes = 0;
        cfg.stream = 0;
        cfg.attrs = attr;
        cfg.numAttrs = 1;
        cudaLaunchKernelEx(&cfg, finalize_reduce_kernel, E, labels, out);
    }
}